// round 4
// baseline (speedup 1.0000x reference)
#include <cuda_runtime.h>
#include <stdint.h>

#define BB 512
#define SS 1024
#define TT 48

__device__ float g_partial[BB];

__device__ __forceinline__ unsigned long long pk2(float x, float y) {
    unsigned long long r;
    asm("mov.b64 %0, {%1,%2};" : "=l"(r) : "f"(x), "f"(y));
    return r;
}
__device__ __forceinline__ void upk2(unsigned long long v, float& x, float& y) {
    asm("mov.b64 {%0,%1}, %2;" : "=f"(x), "=f"(y) : "l"(v));
}
__device__ __forceinline__ unsigned long long fma2(unsigned long long a, unsigned long long b, unsigned long long c) {
    unsigned long long d;
    asm("fma.rn.f32x2 %0, %1, %2, %3;" : "=l"(d) : "l"(a), "l"(b), "l"(c));
    return d;
}
__device__ __forceinline__ unsigned long long add2(unsigned long long a, unsigned long long b) {
    unsigned long long d;
    asm("add.rn.f32x2 %0, %1, %2;" : "=l"(d) : "l"(a), "l"(b));
    return d;
}

// One CTA (64 threads = 2 warps) per batch element.
// warp0 owns output columns 0..31, warp1 lanes 0..15 own columns 32..47.
// warp1 lane 16 computes the gold-path numerator (independent, no recurrence).
// Exchange of the 48-vector p between steps: double-buffered smem + __syncthreads.
__global__ __launch_bounds__(64) void crf_main(
    const float* __restrict__ em,          // [B,S,T]
    const int* __restrict__ tags,          // [B,S]
    const unsigned char* __restrict__ mask,// [B,S] bool OR int32 (auto-detected)
    const float* __restrict__ startT,      // [T]
    const float* __restrict__ endT,        // [T]
    const float* __restrict__ trans)       // [T,T]
{
    __shared__ __align__(16) float sP[2][TT];
    __shared__ float sShift;
    __shared__ float sNum;
    __shared__ float sFin[2];
    __shared__ int   sK;

    const unsigned FULL = 0xffffffffu;
    int tid = threadIdx.x;
    int w = tid >> 5;
    int l = tid & 31;
    int b = blockIdx.x;

    // ---- mask dtype detection + length (monotone mask => popcount) ----
    bool isbool = ((mask[1] | mask[1025] | mask[2049] | mask[3073]) != 0);
    int cnt = 0;
    if (isbool) {
        const uchar4* m4 = reinterpret_cast<const uchar4*>(mask + (size_t)b * SS);
        #pragma unroll
        for (int k = 0; k < 8; k++) {
            uchar4 v = m4[l + 32 * k];
            cnt += v.x + v.y + v.z + v.w;
        }
    } else {
        const int* mi = reinterpret_cast<const int*>(mask) + (size_t)b * SS;
        #pragma unroll
        for (int k = 0; k < 32; k++) cnt += mi[l + 32 * k];
    }
    #pragma unroll
    for (int o = 16; o; o >>= 1) cnt += __shfl_xor_sync(FULL, cnt, o);
    int len = cnt;
    if (len < 1) len = 1;
    if (len > SS) len = SS;

    // ---- lane roles ----
    int  j    = (w == 0) ? l : (32 + (l & 15));   // owned output column
    bool act  = (w == 0) || (l < 16);
    bool isnum = (w == 1) && (l == 16);
    int  slot = (w == 0) ? l : (32 + l);          // smem write slot (w1: l<16 only)

    // ---- E column (exp of transitions) in registers: 24 f32x2 pairs ----
    unsigned long long colJ[24];
    #pragma unroll
    for (int m = 0; m < 24; m++)
        colJ[m] = pk2(__expf(trans[(2 * m) * TT + j]),
                      __expf(trans[(2 * m + 1) * TT + j]));

    const float* emb = em + (size_t)b * SS * TT;

    // ---- init p0 = exp(start + emit0 - shift) ----
    float s0 = startT[j] + emb[j];
    if (w == 0 && l == 0) { sShift = s0; sK = 0; }
    __syncthreads();
    float shift = sShift;
    float p = act ? __expf(s0 - shift) : 0.f;
    if (act) sP[0][slot] = p;

    // ---- numerator init (warp1 lane16) ----
    float num = 0.f;
    int tgp = 0, tg_cur = 0;
    if (isnum) {
        tgp = tags[(size_t)b * SS];
        num = startT[tgp] + emb[tgp];
        tg_cur = tags[(size_t)b * SS + 1];
    }
    __syncthreads();

    // ---- rescale state (uniform across all lanes/warps) ----
    int ksum = 0;     // total applied power-of-2 exponent
    int kpend = 0;    // exponent read from smem, pending application
    float kread = 0.f;

    // ---- emission prefetch ring (depth 4): own column only ----
    float buf[4];
    #pragma unroll
    for (int u = 0; u < 4; u++) buf[u] = emb[(1 + u) * TT + j];

    // ---- main recurrence: p <- (E^T p) * exp(emit_t) * 2^-k ----
    // phases by t&3 : 0 = measure exponent (warp0 lane0 -> sK)
    //                 1 = read sK
    //                 2 = apply (fold 2^-k into emission weight), ksum += k
    for (int t0 = 1; t0 < len; t0 += 4) {
        #pragma unroll
        for (int u = 0; u < 4; u++) {
            int t = t0 + u;                // t&3 == (u+1)&3  (static per u)
            int ph = (u + 1) & 3;
            if (t < len) {
                int rb = (t + 1) & 1;
                int wb = t & 1;

                // emission weight (loaded 4 steps ago), fold rescale at phase 2
                float wt = __expf(buf[u]);
                if (ph == 2) {
                    kpend = (int)kread;
                    float Mf = __uint_as_float((unsigned)(127 - kpend) << 23);
                    wt *= Mf;
                }

                // numerator gathers (warp1 lane16, off the matvec warp)
                float trv = 0.f, emv = 0.f;
                int tg_next = 0;
                if (isnum) {
                    trv = trans[tgp * TT + tg_cur];
                    emv = emb[t * TT + tg_cur];
                    int tn = t + 1; if (tn > SS - 1) tn = SS - 1;
                    tg_next = tags[(size_t)b * SS + tn];
                }

                // prefetch emission for t+4
                int tp = t + 4; if (tp > SS - 1) tp = SS - 1;
                buf[u] = emb[tp * TT + j];

                // matvec: acc_j = sum_i p[i] * E[i][j]  (12 LDS.128 + 24 FMA2)
                const ulonglong2* sp = reinterpret_cast<const ulonglong2*>(&sP[rb][0]);
                unsigned long long a0 = 0, a1 = 0, a2 = 0, a3 = 0;
                #pragma unroll
                for (int q = 0; q < 6; q++) {
                    ulonglong2 v0 = sp[2 * q];
                    ulonglong2 v1 = sp[2 * q + 1];
                    a0 = fma2(v0.x, colJ[4 * q + 0], a0);
                    a1 = fma2(v0.y, colJ[4 * q + 1], a1);
                    a2 = fma2(v1.x, colJ[4 * q + 2], a2);
                    a3 = fma2(v1.y, colJ[4 * q + 3], a3);
                }
                float x0, y0, x1, y1;
                upk2(add2(add2(a0, a1), add2(a2, a3)), x0, y0);
                p = (x0 + y0) * wt;

                // phase bookkeeping
                if (ph == 0) {
                    if (w == 0 && l == 0) {
                        unsigned eb = (__float_as_uint(p) >> 23) & 255u;
                        if (eb < 64u) eb = 64u;
                        if (eb > 190u) eb = 190u;
                        sK = (int)eb - 127;
                    }
                } else if (ph == 1) {
                    kread = (float)sK;
                } else if (ph == 2) {
                    ksum += kpend;
                }

                if (isnum) {
                    num += trv + emv;
                    tgp = tg_cur;
                    tg_cur = tg_next;
                }

                if (act) sP[wb][slot] = p;
                __syncthreads();
            }
        }
    }

    // ---- finalize ----
    float fin = act ? p * __expf(endT[j]) : 0.f;
    #pragma unroll
    for (int o = 16; o; o >>= 1) fin += __shfl_xor_sync(FULL, fin, o);
    if (l == 0) sFin[w] = fin;
    if (isnum) sNum = num + endT[tgp];
    __syncthreads();
    if (tid == 0) {
        float tot = sFin[0] + sFin[1];
        float logZ = __logf(tot) + shift + (float)ksum * 0.69314718055994531f;
        g_partial[b] = logZ - sNum;
    }
}

__global__ void crf_reduce(float* __restrict__ out) {
    __shared__ float s[256];
    int tid = threadIdx.x;
    s[tid] = g_partial[tid] + g_partial[tid + 256];
    __syncthreads();
    #pragma unroll
    for (int o = 128; o > 0; o >>= 1) {
        if (tid < o) s[tid] += s[tid + o];
        __syncthreads();
    }
    if (tid == 0) out[0] = s[0] * (1.0f / (float)BB);
}

extern "C" void kernel_launch(void* const* d_in, const int* in_sizes, int n_in,
                              void* d_out, int out_size) {
    const float*         em   = (const float*)d_in[0];
    const int*           tags = (const int*)d_in[1];
    const unsigned char* mask = (const unsigned char*)d_in[2];
    const float*         st   = (const float*)d_in[3];
    const float*         en   = (const float*)d_in[4];
    const float*         tr   = (const float*)d_in[5];
    crf_main<<<BB, 64>>>(em, tags, mask, st, en, tr);
    crf_reduce<<<1, 256>>>((float*)d_out);
}

// round 8
// speedup vs baseline: 1.0599x; 1.0599x over previous
#include <cuda_runtime.h>
#include <stdint.h>

#define BB 512
#define SS 1024
#define TT 48

__device__ float g_partial[BB];

__device__ __forceinline__ unsigned long long pk2(float x, float y) {
    unsigned long long r;
    asm("mov.b64 %0, {%1,%2};" : "=l"(r) : "f"(x), "f"(y));
    return r;
}
__device__ __forceinline__ void upk2(unsigned long long v, float& x, float& y) {
    asm("mov.b64 {%0,%1}, %2;" : "=f"(x), "=f"(y) : "l"(v));
}
__device__ __forceinline__ unsigned long long fma2(unsigned long long a, unsigned long long b, unsigned long long c) {
    unsigned long long d;
    asm("fma.rn.f32x2 %0, %1, %2, %3;" : "=l"(d) : "l"(a), "l"(b), "l"(c));
    return d;
}
__device__ __forceinline__ unsigned long long add2(unsigned long long a, unsigned long long b) {
    unsigned long long d;
    asm("add.rn.f32x2 %0, %1, %2;" : "=l"(d) : "l"(a), "l"(b));
    return d;
}

// 4 sequences per CTA (256 threads = 8 warps). Team k = warps {2k, 2k+1}.
// Team warp0 owns columns 0..31; warp1 lanes 0..15 own columns 32..47.
// Numerator + lengths computed in a fully parallel prologue (no serial dep).
__global__ __launch_bounds__(256, 1) void crf_main(
    const float* __restrict__ em,          // [B,S,T]
    const int* __restrict__ tags,          // [B,S]
    const unsigned char* __restrict__ mask,// [B,S] bool OR int32 (auto-detected)
    const float* __restrict__ startT,      // [T]
    const float* __restrict__ endT,        // [T]
    const float* __restrict__ trans)       // [T,T]
{
    __shared__ __align__(16) float sP[4][2][TT];
    __shared__ float sShift[4], sNum[4], sFin[8], sRed[8];
    __shared__ int   sCnt[8], sLen[4], sK[4], sLmax;

    const unsigned FULL = 0xffffffffu;
    int tid  = threadIdx.x;
    int w    = tid >> 5;
    int l    = tid & 31;
    int team = tid >> 6;          // 0..3
    int tw   = (tid >> 5) & 1;    // warp within team
    int i64  = tid & 63;          // lane within team
    int b    = blockIdx.x * 4 + team;

    bool isbool = ((mask[1] | mask[1025] | mask[2049] | mask[3073]) != 0);

    const float* embT = em + (size_t)b * SS * TT;
    const int*   tgT  = tags + (size_t)b * SS;

    // ===== parallel prologue: numerator + length (16 t's per thread) =====
    float part = 0.f;
    int mcnt = 0;
    #pragma unroll 4
    for (int k = 0; k < 16; k++) {
        int t = i64 + 64 * k;
        int mk = isbool ? (int)mask[(size_t)b * SS + t]
                        : ((const int*)mask)[(size_t)b * SS + t];
        int tg = tgT[t];
        if (t == 0) {
            part += startT[tg] + embT[tg];
        } else {
            int tgm = tgT[t - 1];
            float c = trans[tgm * TT + tg] + embT[t * TT + tg];
            part += mk ? c : 0.f;
        }
        mcnt += mk ? 1 : 0;
    }
    #pragma unroll
    for (int o = 16; o; o >>= 1) {
        part += __shfl_xor_sync(FULL, part, o);
        mcnt += __shfl_xor_sync(FULL, mcnt, o);
    }
    if (l == 0) { sRed[w] = part; sCnt[w] = mcnt; }
    __syncthreads();
    if (i64 == 0) {
        int len = sCnt[2 * team] + sCnt[2 * team + 1];
        if (len < 1) len = 1;
        if (len > SS) len = SS;
        sLen[team] = len;
        sNum[team] = sRed[2 * team] + sRed[2 * team + 1] + endT[tgT[len - 1]];
        sK[team] = 0;
    }
    __syncthreads();
    if (tid == 0) {
        int m = sLen[0];
        if (sLen[1] > m) m = sLen[1];
        if (sLen[2] > m) m = sLen[2];
        if (sLen[3] > m) m = sLen[3];
        sLmax = m;
    }

    // ===== column assignment + E columns in registers =====
    int  j    = (tw == 0) ? l : (32 + (l & 15));
    bool act0 = (tw == 0) || (l < 16);
    int  slot = (tw == 0) ? l : (32 + (l & 15));

    unsigned long long colJ[24];
    #pragma unroll
    for (int m = 0; m < 24; m++)
        colJ[m] = pk2(__expf(trans[(2 * m) * TT + j]),
                      __expf(trans[(2 * m + 1) * TT + j]));

    // ===== init p0 = exp(start + emit0 - shift) =====
    float s0 = startT[j] + embT[j];
    if (tw == 0 && l == 0) sShift[team] = s0;
    __syncthreads();
    float shift = sShift[team];
    int   lenT  = sLen[team];
    int   Lmax  = sLmax;
    float p = act0 ? __expf(s0 - shift) : 0.f;
    if (act0) sP[team][0][slot] = p;

    float buf[4];
    #pragma unroll
    for (int u = 0; u < 4; u++) buf[u] = embT[(1 + u) * TT + j];

    int ksum = 0, kpend = 0;
    __syncthreads();

    // ===== recurrence: p <- (E^T p) * exp(emit_t) * 2^-k (k lagged by 2) =====
    for (int t0 = 1; t0 < Lmax; t0 += 4) {
        #pragma unroll
        for (int u = 0; u < 4; u++) {
            int t = t0 + u;
            int ph = (u + 1) & 3;      // == t & 3 (t0 % 4 == 1)
            if (t < Lmax) {            // CTA-uniform guard
                if (t < lenT) {        // team-uniform guard
                    float wt = __expf(buf[u]);
                    if (ph == 2)
                        wt *= __uint_as_float((unsigned)(127 - kpend) << 23);

                    int tp = t + 4; if (tp > SS - 1) tp = SS - 1;
                    float nb = embT[tp * TT + j];

                    int rb = (t + 1) & 1, wb = t & 1;
                    const ulonglong2* sp =
                        reinterpret_cast<const ulonglong2*>(&sP[team][rb][0]);
                    unsigned long long a0 = 0, a1 = 0, a2 = 0, a3 = 0;
                    #pragma unroll
                    for (int q = 0; q < 6; q++) {
                        ulonglong2 v0 = sp[2 * q];
                        ulonglong2 v1 = sp[2 * q + 1];
                        a0 = fma2(v0.x, colJ[4 * q + 0], a0);
                        a1 = fma2(v0.y, colJ[4 * q + 1], a1);
                        a2 = fma2(v1.x, colJ[4 * q + 2], a2);
                        a3 = fma2(v1.y, colJ[4 * q + 3], a3);
                    }
                    float x0, y0;
                    upk2(add2(add2(a0, a1), add2(a2, a3)), x0, y0);
                    p = (x0 + y0) * wt;
                    buf[u] = nb;

                    if (ph == 0) {
                        if (tw == 0 && l == 0) {
                            unsigned eb = (__float_as_uint(p) >> 23) & 255u;
                            if (eb < 64u) eb = 64u;
                            if (eb > 190u) eb = 190u;
                            sK[team] = (int)eb - 127;
                        }
                    } else if (ph == 1) {
                        kpend = sK[team];       // written 1 barrier ago
                    } else if (ph == 2) {
                        ksum += kpend;
                    }

                    if (act0) sP[team][wb][slot] = p;
                }
                __syncthreads();
            }
        }
    }

    // ===== finalize =====
    float fin = act0 ? p * __expf(endT[j]) : 0.f;
    #pragma unroll
    for (int o = 16; o; o >>= 1) fin += __shfl_xor_sync(FULL, fin, o);
    if (l == 0) sFin[w] = fin;
    __syncthreads();
    if (i64 == 0) {
        float tot = sFin[2 * team] + sFin[2 * team + 1];
        float logZ = __logf(tot) + shift + (float)ksum * 0.69314718055994531f;
        g_partial[b] = logZ - sNum[team];
    }
}

__global__ void crf_reduce(float* __restrict__ out) {
    __shared__ float s[256];
    int tid = threadIdx.x;
    s[tid] = g_partial[tid] + g_partial[tid + 256];
    __syncthreads();
    #pragma unroll
    for (int o = 128; o > 0; o >>= 1) {
        if (tid < o) s[tid] += s[tid + o];
        __syncthreads();
    }
    if (tid == 0) out[0] = s[0] * (1.0f / (float)BB);
}

extern "C" void kernel_launch(void* const* d_in, const int* in_sizes, int n_in,
                              void* d_out, int out_size) {
    const float*         em   = (const float*)d_in[0];
    const int*           tags = (const int*)d_in[1];
    const unsigned char* mask = (const unsigned char*)d_in[2];
    const float*         st   = (const float*)d_in[3];
    const float*         en   = (const float*)d_in[4];
    const float*         tr   = (const float*)d_in[5];
    crf_main<<<BB / 4, 256>>>(em, tags, mask, st, en, tr);
    crf_reduce<<<1, 256>>>((float*)d_out);
}